// round 16
// baseline (speedup 1.0000x reference)
#include <cuda_runtime.h>
#include <cstdint>
#include <cstddef>

// ---------------------------------------------------------------------------
// ColorHistogramMatchingLoss — R13: C-half split for 4 independent blocks/SM.
//   hist[b,c][i][j] = sum_n w_n * rbf_u(n)[i] * rbf_v(n)[j]
// Block = 128 threads computes a 64x32 half of one C. 8x8 thread tiles
// (1.0 lane-B per lane-FMA), register ping-pong k+1 prefetch in the GEMM,
// CHUNK=128 (prepass = 1 px/thread, raw in regs), 576 blocks single wave,
// fused finalize.
// ---------------------------------------------------------------------------

#define D_HIST 64
#define CHUNK  128
#define SPLITS 6
#define PX_PER_SPLIT 10923           // ceil(65536/6)
#define NCHUNKS 86                   // ceil(10923/128)
#define HIST_BLOCKS (2*8*3*SPLITS*2) // 576 (x2: C halves)
#define EPS_F  1e-6f
#define PLANE  65536
#define HTOT   (2*8*3*D_HIST*D_HIST)

// dynamic smem layout (bytes from base)
#define OFF_A   0u                   // 128 k-rows x 64 f32 = 32768
#define OFF_B   32768u               // 128 k-rows x 32 f32 = 16384
#define OFF_U   49152u               // 128 f32 (u*50)
#define OFF_V   49664u
#define OFF_W   50176u
#define DYN_SMEM 50688               // x4 blocks = 198 KB < 228 KB

__device__ float    g_hist[HTOT];
__device__ unsigned g_done;

// ---- packed f32x2 helpers -------------------------------------------------
static __device__ __forceinline__ unsigned long long pk2(float v) {
    unsigned long long r;
    asm("mov.b64 %0, {%1, %1};" : "=l"(r) : "f"(v));
    return r;
}
static __device__ __forceinline__ void fma2(unsigned long long &d,
                                            unsigned long long a,
                                            unsigned long long b) {
    asm("fma.rn.f32x2 %0, %1, %2, %0;" : "+l"(d) : "l"(a), "l"(b));
}
static __device__ __forceinline__ void lds_pair(unsigned long long &a,
                                                unsigned long long &b,
                                                unsigned addr) {
    asm volatile("ld.shared.v2.u64 {%0, %1}, [%2];"
                 : "=l"(a), "=l"(b) : "r"(addr));
}

// ---------------------------------------------------------------------------
__global__ void zero_kernel() {
    int i = blockIdx.x * blockDim.x + threadIdx.x;
    if (i < HTOT) g_hist[i] = 0.0f;
    if (i == 0) g_done = 0u;
}

// ---------------------------------------------------------------------------
__global__ __launch_bounds__(128, 4)
void hist_kernel(const float* __restrict__ x, const float* __restrict__ y,
                 float* __restrict__ out)
{
    extern __shared__ char P[];
    const unsigned sb = (unsigned)__cvta_generic_to_shared(P);

    const int bx     = blockIdx.x;
    const int split  = bx % SPLITS;
    const int tmp    = bx / SPLITS;
    const int half   = tmp & 1;
    const int r1     = tmp >> 1;
    const int c      = r1 % 3;
    const int r2     = r1 / 3;
    const int b      = r2 & 7;
    const int tensor = r2 >> 3;
    const float* img = (tensor ? y : x) + (size_t)b * 3u * PLANE;

    const int base = split * PX_PER_SPLIT;
    const int pend = min(base + PX_PER_SPLIT, PLANE);

    const int t = threadIdx.x;

    // fill-phase mapping
    const int   colA = t & 63;                 // A bin column (0..63)
    const int   kha  = t >> 6;                 // A k-half (0,1)
    const int   colB = t & 31;                 // B bin column within half
    const int   kqb  = t >> 5;                 // B k-quarter (0..3)
    const float csA  = fmaf((float)colA, 300.0f/63.0f, -150.0f);
    const float csB  = fmaf((float)(half*32 + colB), 300.0f/63.0f, -150.0f);

    // GEMM mapping: 4 k-subgroups of 32 threads; 8x8 tile over 64x32 C-half
    const int s     = t & 31;
    const int i0    = (s >> 2) * 8;            // C row base (0..56)
    const int j0    = (s & 3) * 8;             // C col base (0..24)
    const int kbase = (t >> 5) * 32;           // 32 k-steps per subgroup

    unsigned long long acc[8][4];
    #pragma unroll
    for (int i = 0; i < 8; i++)
        #pragma unroll
        for (int j = 0; j < 4; j++) acc[i][j] = 0ull;

    float* up  = (float*)(P + OFF_U);
    float* vp  = (float*)(P + OFF_V);
    float* wp_ = (float*)(P + OFF_W);

    // ---- raw pixel loads (regs only; 1 px per thread per chunk) -----------
    float pr, pg, pb_;
    {
        int p = base + t;
        bool v = p < pend;
        pr  = v ? img[p]           : 1.0f;
        pg  = v ? img[PLANE + p]   : 1.0f;
        pb_ = v ? img[2*PLANE + p] : 1.0f;
    }

    for (int chk = 0; chk < NCHUNKS; ++chk) {
        // ---- prepass: this thread's pixel -> u/v/w smem ----
        {
            int p = base + chk * CHUNK + t;
            bool valid = p < pend;
            float rr = pr + EPS_F, gg = pg + EPS_F, bb = pb_ + EPS_F;
            float lr = logf(rr), lg = logf(gg), lb = logf(bb);
            float a = lr - lg, d2 = lr - lb;
            float uu, vv;
            if (c == 0)      { uu =  a;  vv = d2;     }
            else if (c == 1) { uu = -a;  vv = d2 - a; }
            else             { uu = -d2; vv = a - d2; }
            up[t]  = uu * 50.0f;
            vp[t]  = vv * 50.0f;
            wp_[t] = valid ? sqrtf(fmaf(rr, rr, fmaf(gg, gg, bb*bb))) : 0.0f;
        }
        // issue next chunk's raw loads (consumed next iteration)
        if (chk + 1 < NCHUNKS) {
            int p = base + (chk + 1) * CHUNK + t;
            bool v = p < pend;
            pr  = v ? img[p]           : 1.0f;
            pg  = v ? img[PLANE + p]   : 1.0f;
            pb_ = v ? img[2*PLANE + p] : 1.0f;
        }
        __syncthreads();

        // ---- fill A[k][i] (w-weighted rbf_u) and B[k][j] (rbf_v) ----
        {
            float* Ap = (float*)(P + OFF_A) + (kha * 64) * D_HIST + colA;
            const float* ua = up  + kha * 64;
            const float* wa = wp_ + kha * 64;
            #pragma unroll 8
            for (int k = 0; k < 64; k++) {
                float tt = ua[k] - csA;
                Ap[k * D_HIST] = __fdividef(wa[k], fmaf(tt, tt, 1.0f));
            }
            float* Bp = (float*)(P + OFF_B) + (kqb * 32) * 32 + colB;
            const float* vb = vp + kqb * 32;
            #pragma unroll 8
            for (int k = 0; k < 32; k++) {
                float tt = vb[k] - csB;
                Bp[k * 32] = __fdividef(1.0f, fmaf(tt, tt, 1.0f));
            }
        }
        __syncthreads();

        // ---- GEMM: 32 k-steps, register ping-pong k+1 prefetch ----
        {
            unsigned aA = sb + OFF_A + (unsigned)kbase*256u + (unsigned)i0*4u;
            unsigned aB = sb + OFF_B + (unsigned)kbase*128u + (unsigned)j0*4u;
            float4 a0c, a1c, a0n, a1n;
            unsigned long long b0c,b1c,b2c,b3c, b0n,b1n,b2n,b3n;
            // preload k-step 0
            a0c = *(const float4*)(P + (size_t)(aA - sb));
            a1c = *(const float4*)(P + (size_t)(aA - sb) + 16u);
            lds_pair(b0c, b1c, aB);
            lds_pair(b2c, b3c, aB + 16u);

            #define FMA_BLOCK(A0, A1, B0, B1, B2, B3) do {                    \
                unsigned long long pa;                                        \
                pa = pk2(A0.x); fma2(acc[0][0],pa,B0); fma2(acc[0][1],pa,B1); fma2(acc[0][2],pa,B2); fma2(acc[0][3],pa,B3); \
                pa = pk2(A0.y); fma2(acc[1][0],pa,B0); fma2(acc[1][1],pa,B1); fma2(acc[1][2],pa,B2); fma2(acc[1][3],pa,B3); \
                pa = pk2(A0.z); fma2(acc[2][0],pa,B0); fma2(acc[2][1],pa,B1); fma2(acc[2][2],pa,B2); fma2(acc[2][3],pa,B3); \
                pa = pk2(A0.w); fma2(acc[3][0],pa,B0); fma2(acc[3][1],pa,B1); fma2(acc[3][2],pa,B2); fma2(acc[3][3],pa,B3); \
                pa = pk2(A1.x); fma2(acc[4][0],pa,B0); fma2(acc[4][1],pa,B1); fma2(acc[4][2],pa,B2); fma2(acc[4][3],pa,B3); \
                pa = pk2(A1.y); fma2(acc[5][0],pa,B0); fma2(acc[5][1],pa,B1); fma2(acc[5][2],pa,B2); fma2(acc[5][3],pa,B3); \
                pa = pk2(A1.z); fma2(acc[6][0],pa,B0); fma2(acc[6][1],pa,B1); fma2(acc[6][2],pa,B2); fma2(acc[6][3],pa,B3); \
                pa = pk2(A1.w); fma2(acc[7][0],pa,B0); fma2(acc[7][1],pa,B1); fma2(acc[7][2],pa,B2); fma2(acc[7][3],pa,B3); \
            } while (0)

            #pragma unroll
            for (int kk = 0; kk < 32; kk += 2) {
                // prefetch kk+1 while computing kk
                a0n = *(const float4*)(P + (size_t)(aA - sb) + 256u);
                a1n = *(const float4*)(P + (size_t)(aA - sb) + 272u);
                lds_pair(b0n, b1n, aB + 128u);
                lds_pair(b2n, b3n, aB + 144u);
                FMA_BLOCK(a0c, a1c, b0c, b1c, b2c, b3c);
                // prefetch kk+2 while computing kk+1
                if (kk + 2 < 32) {
                    a0c = *(const float4*)(P + (size_t)(aA - sb) + 512u);
                    a1c = *(const float4*)(P + (size_t)(aA - sb) + 528u);
                    lds_pair(b0c, b1c, aB + 256u);
                    lds_pair(b2c, b3c, aB + 272u);
                }
                FMA_BLOCK(a0n, a1n, b0n, b1n, b2n, b3n);
                aA += 512u; aB += 256u;
            }
            #undef FMA_BLOCK
        }
        __syncthreads();   // A/B/uvw reusable
    }

    // ---- combine 4 k-subgroup partials in shared, then RED.global --------
    float* Csh = (float*)P;                    // reuse A region (8 KB used)
    for (int i = t; i < 64 * 32; i += 128) Csh[i] = 0.0f;
    __syncthreads();
    #pragma unroll
    for (int ii = 0; ii < 8; ii++) {
        #pragma unroll
        for (int jj = 0; jj < 4; jj++) {
            unsigned long long v2 = acc[ii][jj];
            float lo = __uint_as_float((unsigned)(v2 & 0xffffffffull));
            float hi = __uint_as_float((unsigned)(v2 >> 32));
            atomicAdd(&Csh[(i0 + ii) * 32 + j0 + 2*jj    ], lo);
            atomicAdd(&Csh[(i0 + ii) * 32 + j0 + 2*jj + 1], hi);
        }
    }
    __syncthreads();
    {
        float* dst = g_hist + (size_t)(((tensor * 8) + b) * 3 + c) * (D_HIST*D_HIST);
        for (int i = t; i < 64 * 32; i += 128) {
            int row = i >> 5, col = i & 31;
            atomicAdd(&dst[row * D_HIST + half * 32 + col], Csh[i]);
        }
    }

    // ---- fused finalize: last block reduces ------------------------------
    __threadfence();
    __shared__ unsigned s_last;
    if (t == 0) s_last = (atomicAdd(&g_done, 1u) == (unsigned)(HIST_BLOCKS - 1));
    __syncthreads();
    if (!s_last) return;

    __shared__ float s_red[4];
    __shared__ float s_inv[16];
    __shared__ float s_loss;
    const int lane = t & 31, wp = t >> 5;
    const int PER_B = 3 * D_HIST * D_HIST;     // 12288
    if (t == 0) s_loss = 0.0f;

    for (int gg2 = 0; gg2 < 16; gg2++) {       // per-hist totals
        const float* h = g_hist + (size_t)gg2 * PER_B;
        float ssum = 0.0f;
        for (int i = t; i < PER_B; i += 128) ssum += h[i];
        #pragma unroll
        for (int o = 16; o > 0; o >>= 1) ssum += __shfl_down_sync(0xffffffffu, ssum, o);
        if (lane == 0) s_red[wp] = ssum;
        __syncthreads();
        if (t == 0)
            s_inv[gg2] = 1.0f / (s_red[0] + s_red[1] + s_red[2] + s_red[3]);
        __syncthreads();
    }

    for (int bb2 = 0; bb2 < 8; bb2++) {
        const float* hx = g_hist + (size_t)bb2 * PER_B;
        const float* hy = g_hist + (size_t)(8 + bb2) * PER_B;
        float ix = s_inv[bb2], iy = s_inv[8 + bb2];
        float a2 = 0.0f;
        for (int i = t; i < PER_B; i += 128) {
            float d = sqrtf(hy[i] * iy) - sqrtf(hx[i] * ix);
            a2 = fmaf(d, d, a2);
        }
        #pragma unroll
        for (int o = 16; o > 0; o >>= 1) a2 += __shfl_down_sync(0xffffffffu, a2, o);
        if (lane == 0) s_red[wp] = a2;
        __syncthreads();
        if (t == 0)
            s_loss += sqrtf((s_red[0] + s_red[1] + s_red[2] + s_red[3]) * 0.5f);
        __syncthreads();
    }
    if (t == 0) out[0] = s_loss * 0.125f;
}

// ---------------------------------------------------------------------------
extern "C" void kernel_launch(void* const* d_in, const int* in_sizes, int n_in,
                              void* d_out, int out_size) {
    (void)in_sizes; (void)n_in; (void)out_size;
    const float* x = (const float*)d_in[0];
    const float* y = (const float*)d_in[1];

    cudaFuncSetAttribute((const void*)hist_kernel,
                         cudaFuncAttributeMaxDynamicSharedMemorySize, DYN_SMEM);

    zero_kernel<<<(HTOT + 1023) / 1024, 1024>>>();
    hist_kernel<<<HIST_BLOCKS, 128, DYN_SMEM>>>(x, y, (float*)d_out);
}